// round 4
// baseline (speedup 1.0000x reference)
#include <cuda_runtime.h>
#include <math.h>

#define S_SEG 256
#define T_TOK 512
#define BERT  768
#define POSD  128
#define H1    1024
#define NCLS  6
#define NSEG  64
#define KSLICES 8
#define TSLICES 8
#define TCHUNK  (T_TOK / TSLICES)   // 64

// Scratch (no allocations allowed) — device globals.
__device__ float g_pacc[TSLICES * S_SEG * BERT];   // unnormalized partial accumulators
__device__ float g_pm[TSLICES * S_SEG];            // partial max
__device__ float g_pd[TSLICES * S_SEG];            // partial denom
__device__ float g_segvec[S_SEG * BERT];
__device__ float g_vecs[NSEG * BERT];
__device__ float g_h1[NSEG * H1];
__device__ float g_h2[NSEG * H1];
__device__ float g_part[KSLICES * NSEG * H1];

// ---------------------------------------------------------------------------
// Kernel 1a: split-T online-softmax pooling partials.
// grid (S=256, TSLICES=8) = 2048 CTAs, 256 threads.
// tid<192 own 4 emb channels (float4); tid in [192,224) own 4 pos channels.
// Each CTA handles 64 tokens (8 rounds of 8). emb read exactly once.
// ---------------------------------------------------------------------------
__global__ __launch_bounds__(256)
void pool_part_kernel(const float* __restrict__ emb,
                      const float* __restrict__ pos,
                      const float* __restrict__ Wa,
                      const float* __restrict__ ba)
{
    const int s     = blockIdx.x;
    const int slice = blockIdx.y;
    const int tid   = threadIdx.x;
    const int lane  = tid & 31;
    const int wid   = tid >> 5;

    __shared__ float s_wpart[8][8];
    __shared__ float s_logits[8];

    float4 w = make_float4(0.f, 0.f, 0.f, 0.f);
    if (tid < 192)      w = *(const float4*)(Wa + 4 * tid);
    else if (tid < 224) w = *(const float4*)(Wa + BERT + 4 * (tid - 192));
    const float bias = ba[0];

    const int tbase = slice * TCHUNK;
    const float* erow = emb + (size_t)s * T_TOK * BERT;
    const float* prow = pos + (size_t)s * T_TOK * POSD;

    float m = -1e30f;
    float d = 0.f;
    float ax = 0.f, ay = 0.f, az = 0.f, aw = 0.f;

    for (int t0 = tbase; t0 < tbase + TCHUNK; t0 += 8) {
        float4 x[8];
        float  part[8];
        #pragma unroll
        for (int k = 0; k < 8; k++) {
            float4 v = make_float4(0.f, 0.f, 0.f, 0.f);
            if (tid < 192)
                v = *(const float4*)(erow + (size_t)(t0 + k) * BERT + 4 * tid);
            else if (tid < 224)
                v = *(const float4*)(prow + (size_t)(t0 + k) * POSD + 4 * (tid - 192));
            x[k] = v;
            part[k] = v.x * w.x + v.y * w.y + v.z * w.z + v.w * w.w;
        }
        #pragma unroll
        for (int o = 16; o > 0; o >>= 1) {
            #pragma unroll
            for (int k = 0; k < 8; k++)
                part[k] += __shfl_xor_sync(0xffffffffu, part[k], o);
        }
        if (lane == 0) {
            #pragma unroll
            for (int k = 0; k < 8; k++) s_wpart[wid][k] = part[k];
        }
        __syncthreads();
        if (tid < 8) {
            float sum = bias;
            #pragma unroll
            for (int ww = 0; ww < 8; ww++) sum += s_wpart[ww][tid];
            s_logits[tid] = sum;
        }
        __syncthreads();

        float a[8];
        #pragma unroll
        for (int k = 0; k < 8; k++) a[k] = s_logits[k];

        float mn = a[0];
        #pragma unroll
        for (int k = 1; k < 8; k++) mn = fmaxf(mn, a[k]);
        const float m_new = fmaxf(m, mn);
        const float scale = __expf(m - m_new);
        float p[8];
        float psum = 0.f;
        #pragma unroll
        for (int k = 0; k < 8; k++) { p[k] = __expf(a[k] - m_new); psum += p[k]; }
        d = d * scale + psum;
        float nx = ax * scale, ny = ay * scale, nz = az * scale, nw2 = aw * scale;
        #pragma unroll
        for (int k = 0; k < 8; k++) {
            nx += p[k] * x[k].x;
            ny += p[k] * x[k].y;
            nz += p[k] * x[k].z;
            nw2 += p[k] * x[k].w;
        }
        ax = nx; ay = ny; az = nz; aw = nw2;
        m = m_new;
    }

    const int ps = slice * S_SEG + s;
    if (tid < 192) {
        float4 o = make_float4(ax, ay, az, aw);
        *(float4*)(g_pacc + (size_t)ps * BERT + 4 * tid) = o;
    }
    if (tid == 0) {
        g_pm[ps] = m;
        g_pd[ps] = d;
    }
}

// ---------------------------------------------------------------------------
// Kernel 1b: merge TSLICES partials per segment (flash-attn style merge).
// grid 256, 192 threads (one float4 of the 768 channels each).
// ---------------------------------------------------------------------------
__global__ __launch_bounds__(192)
void pool_merge_kernel()
{
    const int s   = blockIdx.x;
    const int tid = threadIdx.x;

    float m[TSLICES], d[TSLICES];
    #pragma unroll
    for (int z = 0; z < TSLICES; z++) {
        m[z] = g_pm[z * S_SEG + s];
        d[z] = g_pd[z * S_SEG + s];
    }
    float M = m[0];
    #pragma unroll
    for (int z = 1; z < TSLICES; z++) M = fmaxf(M, m[z]);
    float sc[TSLICES];
    float D = 0.f;
    #pragma unroll
    for (int z = 0; z < TSLICES; z++) { sc[z] = __expf(m[z] - M); D += d[z] * sc[z]; }
    const float inv = 1.f / D;

    float4 acc = make_float4(0.f, 0.f, 0.f, 0.f);
    #pragma unroll
    for (int z = 0; z < TSLICES; z++) {
        float4 p = *(const float4*)(g_pacc + (size_t)(z * S_SEG + s) * BERT + 4 * tid);
        acc.x += sc[z] * p.x;
        acc.y += sc[z] * p.y;
        acc.z += sc[z] * p.z;
        acc.w += sc[z] * p.w;
    }
    float4 o = make_float4(acc.x * inv, acc.y * inv, acc.z * inv, acc.w * inv);
    *(float4*)(g_segvec + (size_t)s * BERT + 4 * tid) = o;
}

// ---------------------------------------------------------------------------
// Kernel 2: deterministic segment sum (sorted ids). One CTA per segment g.
// ---------------------------------------------------------------------------
__global__ __launch_bounds__(256)
void segsum_kernel(const int* __restrict__ seg)
{
    __shared__ int sid[S_SEG];
    const int g = blockIdx.x;
    const int tid = threadIdx.x;
    sid[tid] = seg[tid];
    __syncthreads();

    float a0 = 0.f, a1 = 0.f, a2 = 0.f;
    for (int s = 0; s < S_SEG; s++) {
        if (sid[s] == g) {
            const float* r = g_segvec + (size_t)s * BERT;
            a0 += r[tid];
            a1 += r[tid + 256];
            a2 += r[tid + 512];
        }
    }
    g_vecs[g * BERT + tid]       = a0;
    g_vecs[g * BERT + tid + 256] = a1;
    g_vecs[g * BERT + tid + 512] = a2;
}

// ---------------------------------------------------------------------------
// Kernels 3/4: register-tiled split-K GEMM. grid (16 colblocks, KSLICES=8).
// CTA computes ALL 64 rows x 64 cols for its K-chunk. 128 threads:
// thread = (colgroup c=tid&7 -> 8 cols, rowgroup r=tid>>3 -> 4 rows)
// => 32 accumulators, 32 FMA per k-step vs 2 W-float4 + 4 smem loads.
// W is read exactly once from L2/DRAM.
// ---------------------------------------------------------------------------
template <int K>
__global__ __launch_bounds__(128)
void mlp_splitk_kernel(const float* __restrict__ in, const float* __restrict__ W,
                       float* __restrict__ part)
{
    constexpr int CHUNK = K / KSLICES;   // 96 or 128
    constexpr int TP    = CHUNK + 1;     // pad to break LDS bank conflicts
    __shared__ float tile[NSEG * TP];

    const int tid   = threadIdx.x;
    const int c     = tid & 7;           // col group (8 cols)
    const int r     = tid >> 3;          // row group (4 rows), 0..15
    const int jbase = blockIdx.x * 64 + c * 8;
    const int k0    = blockIdx.y * CHUNK;

    // Stage A chunk: in[row][k0+cc] -> tile[row*TP+cc] (coalesced global reads)
    for (int e = tid; e < NSEG * CHUNK; e += 128) {
        int rr = e / CHUNK;
        int cc = e - rr * CHUNK;
        tile[rr * TP + cc] = in[(size_t)rr * K + k0 + cc];
    }
    __syncthreads();

    float4 accA[4], accB[4];
    #pragma unroll
    for (int i = 0; i < 4; i++) {
        accA[i] = make_float4(0.f, 0.f, 0.f, 0.f);
        accB[i] = make_float4(0.f, 0.f, 0.f, 0.f);
    }

    const float* wp = W + (size_t)k0 * H1 + jbase;
    const float* xp = tile + (r * 4) * TP;

    #pragma unroll 8
    for (int kk = 0; kk < CHUNK; kk++) {
        const float4 w0 = *(const float4*)(wp + (size_t)kk * H1);
        const float4 w1 = *(const float4*)(wp + (size_t)kk * H1 + 4);
        #pragma unroll
        for (int i = 0; i < 4; i++) {
            const float xv = xp[i * TP + kk];
            accA[i].x += xv * w0.x;
            accA[i].y += xv * w0.y;
            accA[i].z += xv * w0.z;
            accA[i].w += xv * w0.w;
            accB[i].x += xv * w1.x;
            accB[i].y += xv * w1.y;
            accB[i].z += xv * w1.z;
            accB[i].w += xv * w1.w;
        }
    }

    float* pb = part + (size_t)blockIdx.y * NSEG * H1 + jbase;
    #pragma unroll
    for (int i = 0; i < 4; i++) {
        *(float4*)(pb + (size_t)(r * 4 + i) * H1)     = accA[i];
        *(float4*)(pb + (size_t)(r * 4 + i) * H1 + 4) = accB[i];
    }
}

// Reduce partials + bias + LeakyReLU(0.01). One CTA per row (64), 256 threads.
__global__ __launch_bounds__(256)
void mlp_reduce_kernel(const float* __restrict__ b, float* __restrict__ out)
{
    const int row = blockIdx.x;
    const int c4  = threadIdx.x * 4;
    float4 a = make_float4(0.f, 0.f, 0.f, 0.f);
    #pragma unroll
    for (int z = 0; z < KSLICES; z++) {
        float4 p = *(const float4*)(g_part + (size_t)z * NSEG * H1 + (size_t)row * H1 + c4);
        a.x += p.x; a.y += p.y; a.z += p.z; a.w += p.w;
    }
    const float4 bb = *(const float4*)(b + c4);
    float4 o;
    o.x = a.x + bb.x; o.x = o.x > 0.f ? o.x : 0.01f * o.x;
    o.y = a.y + bb.y; o.y = o.y > 0.f ? o.y : 0.01f * o.y;
    o.z = a.z + bb.z; o.z = o.z > 0.f ? o.z : 0.01f * o.z;
    o.w = a.w + bb.w; o.w = o.w > 0.f ? o.w : 0.01f * o.w;
    *(float4*)(out + (size_t)row * H1 + c4) = o;
}

// ---------------------------------------------------------------------------
// Kernel 5: head (64,1024)@(1024,6) + bias, sigmoid. One warp per segment.
// ---------------------------------------------------------------------------
__global__ __launch_bounds__(32)
void head_kernel(const float* __restrict__ W3, const float* __restrict__ b3,
                 float* __restrict__ out)
{
    const int g    = blockIdx.x;
    const int lane = threadIdx.x;
    float p[NCLS] = {0.f, 0.f, 0.f, 0.f, 0.f, 0.f};

    for (int k = lane; k < H1; k += 32) {
        float x = g_h2[(size_t)g * H1 + k];
        #pragma unroll
        for (int j = 0; j < NCLS; j++)
            p[j] += x * W3[k * NCLS + j];
    }
    #pragma unroll
    for (int j = 0; j < NCLS; j++) {
        #pragma unroll
        for (int o = 16; o > 0; o >>= 1)
            p[j] += __shfl_xor_sync(0xffffffffu, p[j], o);
    }
    if (lane < NCLS) {
        float v = p[lane] + b3[lane];
        out[g * NCLS + lane] = 1.f / (1.f + expf(-v));
    }
}

// ---------------------------------------------------------------------------
extern "C" void kernel_launch(void* const* d_in, const int* in_sizes, int n_in,
                              void* d_out, int out_size)
{
    (void)in_sizes; (void)n_in; (void)out_size;
    const float* emb = (const float*)d_in[0];
    const float* pos = (const float*)d_in[1];
    const float* Wa  = (const float*)d_in[2];
    const float* ba  = (const float*)d_in[3];
    const float* W1  = (const float*)d_in[4];
    const float* b1  = (const float*)d_in[5];
    const float* W2  = (const float*)d_in[6];
    const float* b2  = (const float*)d_in[7];
    const float* W3  = (const float*)d_in[8];
    const float* b3  = (const float*)d_in[9];
    const int*   seg = (const int*)d_in[10];
    float* out = (float*)d_out;

    void *p_vecs = nullptr, *p_h1 = nullptr, *p_h2 = nullptr, *p_part = nullptr;
    cudaGetSymbolAddress(&p_vecs, g_vecs);
    cudaGetSymbolAddress(&p_h1, g_h1);
    cudaGetSymbolAddress(&p_h2, g_h2);
    cudaGetSymbolAddress(&p_part, g_part);

    pool_part_kernel<<<dim3(S_SEG, TSLICES), 256>>>(emb, pos, Wa, ba);
    pool_merge_kernel<<<S_SEG, 192>>>();
    segsum_kernel<<<NSEG, 256>>>(seg);

    mlp_splitk_kernel<BERT><<<dim3(16, KSLICES), 128>>>(
        (const float*)p_vecs, W1, (float*)p_part);
    mlp_reduce_kernel<<<NSEG, 256>>>(b1, (float*)p_h1);

    mlp_splitk_kernel<H1><<<dim3(16, KSLICES), 128>>>(
        (const float*)p_h1, W2, (float*)p_part);
    mlp_reduce_kernel<<<NSEG, 256>>>(b2, (float*)p_h2);

    head_kernel<<<NSEG, 32>>>(W3, b3, out);
}

// round 5
// speedup vs baseline: 1.3778x; 1.3778x over previous
#include <cuda_runtime.h>
#include <math.h>

#define S_SEG 256
#define T_TOK 512
#define BERT  768
#define POSD  128
#define H1    1024
#define NCLS  6
#define NSEG  64
#define KSLICES 8
#define TSLICES 16
#define TCHUNK  (T_TOK / TSLICES)   // 32

// Scratch (no allocations allowed) — device globals.
__device__ float g_pacc[TSLICES * S_SEG * BERT];   // unnormalized partial accumulators
__device__ float g_pm[TSLICES * S_SEG];            // partial max
__device__ float g_pd[TSLICES * S_SEG];            // partial denom
__device__ float g_segvec[S_SEG * BERT];
__device__ float g_vecs[NSEG * BERT];
__device__ float g_h1[NSEG * H1];
__device__ float g_h2[NSEG * H1];
__device__ float g_part[KSLICES * NSEG * H1];

// ---------------------------------------------------------------------------
// Kernel 1a: split-T online-softmax pooling partials.
// Launched in 4 chunks of grid (S=256, 4). slice = slice0 + blockIdx.y.
// 256 threads: tid<192 own 4 emb channels (float4); [192,224) own pos.
// Each CTA handles 32 tokens (4 rounds of 8). One barrier per round.
// ---------------------------------------------------------------------------
__global__ __launch_bounds__(256)
void pool_part_kernel(const float* __restrict__ emb,
                      const float* __restrict__ pos,
                      const float* __restrict__ Wa,
                      const float* __restrict__ ba,
                      int slice0)
{
    const int s     = blockIdx.x;
    const int slice = slice0 + blockIdx.y;
    const int tid   = threadIdx.x;
    const int lane  = tid & 31;
    const int wid   = tid >> 5;

    __shared__ float s_wpart[8][8];   // [warp][token]

    float4 w = make_float4(0.f, 0.f, 0.f, 0.f);
    if (tid < 192)      w = *(const float4*)(Wa + 4 * tid);
    else if (tid < 224) w = *(const float4*)(Wa + BERT + 4 * (tid - 192));
    const float bias = ba[0];

    const int tbase = slice * TCHUNK;
    const float* erow = emb + (size_t)s * T_TOK * BERT;
    const float* prow = pos + (size_t)s * T_TOK * POSD;

    float m = -1e30f;
    float d = 0.f;
    float ax = 0.f, ay = 0.f, az = 0.f, aw = 0.f;

    for (int t0 = tbase; t0 < tbase + TCHUNK; t0 += 8) {
        float4 x[8];
        float  part[8];
        #pragma unroll
        for (int k = 0; k < 8; k++) {
            float4 v = make_float4(0.f, 0.f, 0.f, 0.f);
            if (tid < 192)
                v = *(const float4*)(erow + (size_t)(t0 + k) * BERT + 4 * tid);
            else if (tid < 224)
                v = *(const float4*)(prow + (size_t)(t0 + k) * POSD + 4 * (tid - 192));
            x[k] = v;
            part[k] = v.x * w.x + v.y * w.y + v.z * w.z + v.w * w.w;
        }
        #pragma unroll
        for (int o = 16; o > 0; o >>= 1) {
            #pragma unroll
            for (int k = 0; k < 8; k++)
                part[k] += __shfl_xor_sync(0xffffffffu, part[k], o);
        }
        __syncthreads();   // protect s_wpart reuse from previous round
        if (lane == 0) {
            #pragma unroll
            for (int k = 0; k < 8; k++) s_wpart[wid][k] = part[k];
        }
        __syncthreads();

        // every thread sums the 8 warp partials itself (broadcast LDS)
        float a[8];
        #pragma unroll
        for (int k = 0; k < 8; k++) a[k] = bias;
        #pragma unroll
        for (int ww = 0; ww < 8; ww++) {
            const float4 p0 = *(const float4*)&s_wpart[ww][0];
            const float4 p1 = *(const float4*)&s_wpart[ww][4];
            a[0] += p0.x; a[1] += p0.y; a[2] += p0.z; a[3] += p0.w;
            a[4] += p1.x; a[5] += p1.y; a[6] += p1.z; a[7] += p1.w;
        }

        float mn = a[0];
        #pragma unroll
        for (int k = 1; k < 8; k++) mn = fmaxf(mn, a[k]);
        const float m_new = fmaxf(m, mn);
        const float scale = __expf(m - m_new);
        float p[8];
        float psum = 0.f;
        #pragma unroll
        for (int k = 0; k < 8; k++) { p[k] = __expf(a[k] - m_new); psum += p[k]; }
        d = d * scale + psum;
        float nx = ax * scale, ny = ay * scale, nz = az * scale, nw2 = aw * scale;
        #pragma unroll
        for (int k = 0; k < 8; k++) {
            nx += p[k] * x[k].x;
            ny += p[k] * x[k].y;
            nz += p[k] * x[k].z;
            nw2 += p[k] * x[k].w;
        }
        ax = nx; ay = ny; az = nz; aw = nw2;
        m = m_new;
    }

    const int ps = slice * S_SEG + s;
    if (tid < 192) {
        float4 o = make_float4(ax, ay, az, aw);
        *(float4*)(g_pacc + (size_t)ps * BERT + 4 * tid) = o;
    }
    if (tid == 0) {
        g_pm[ps] = m;
        g_pd[ps] = d;
    }
}

// ---------------------------------------------------------------------------
// Kernel 1b: merge TSLICES partials per segment (flash-attn style merge).
// ---------------------------------------------------------------------------
__global__ __launch_bounds__(192)
void pool_merge_kernel()
{
    const int s   = blockIdx.x;
    const int tid = threadIdx.x;

    float m[TSLICES], d[TSLICES];
    #pragma unroll
    for (int z = 0; z < TSLICES; z++) {
        m[z] = g_pm[z * S_SEG + s];
        d[z] = g_pd[z * S_SEG + s];
    }
    float M = m[0];
    #pragma unroll
    for (int z = 1; z < TSLICES; z++) M = fmaxf(M, m[z]);
    float sc[TSLICES];
    float D = 0.f;
    #pragma unroll
    for (int z = 0; z < TSLICES; z++) { sc[z] = __expf(m[z] - M); D += d[z] * sc[z]; }
    const float inv = 1.f / D;

    float4 acc = make_float4(0.f, 0.f, 0.f, 0.f);
    #pragma unroll
    for (int z = 0; z < TSLICES; z++) {
        float4 p = *(const float4*)(g_pacc + (size_t)(z * S_SEG + s) * BERT + 4 * tid);
        acc.x += sc[z] * p.x;
        acc.y += sc[z] * p.y;
        acc.z += sc[z] * p.z;
        acc.w += sc[z] * p.w;
    }
    float4 o = make_float4(acc.x * inv, acc.y * inv, acc.z * inv, acc.w * inv);
    *(float4*)(g_segvec + (size_t)s * BERT + 4 * tid) = o;
}

// ---------------------------------------------------------------------------
// Kernel 2: deterministic segment sum (sorted ids). One CTA per segment g.
// ---------------------------------------------------------------------------
__global__ __launch_bounds__(256)
void segsum_kernel(const int* __restrict__ seg)
{
    __shared__ int sid[S_SEG];
    const int g = blockIdx.x;
    const int tid = threadIdx.x;
    sid[tid] = seg[tid];
    __syncthreads();

    float a0 = 0.f, a1 = 0.f, a2 = 0.f;
    for (int s = 0; s < S_SEG; s++) {
        if (sid[s] == g) {
            const float* r = g_segvec + (size_t)s * BERT;
            a0 += r[tid];
            a1 += r[tid + 256];
            a2 += r[tid + 512];
        }
    }
    g_vecs[g * BERT + tid]       = a0;
    g_vecs[g * BERT + tid + 256] = a1;
    g_vecs[g * BERT + tid + 512] = a2;
}

// ---------------------------------------------------------------------------
// Kernels 3/4: split-K GEMM partials (R3 config — measured fastest).
// grid (16 colblocks, 8 rowblocks, KSLICES=8) = 1024 CTAs, 128 threads.
// ---------------------------------------------------------------------------
template <int K>
__global__ __launch_bounds__(128)
void mlp_splitk_kernel(const float* __restrict__ in, const float* __restrict__ W,
                       float* __restrict__ part)
{
    constexpr int CHUNK = K / KSLICES;   // 96 or 128
    __shared__ float tile[8 * CHUNK];
    const int tid   = threadIdx.x;
    const int q     = tid & 15;
    const int r     = tid >> 4;
    const int jbase = blockIdx.x * 64 + q * 4;
    const int rbase = blockIdx.y * 8;
    const int k0    = blockIdx.z * CHUNK;

    for (int e = tid; e < 8 * CHUNK; e += 128) {
        int rr = e / CHUNK;
        int cc = e - rr * CHUNK;
        tile[e] = in[(size_t)(rbase + rr) * K + k0 + cc];
    }
    __syncthreads();

    float4 acc = make_float4(0.f, 0.f, 0.f, 0.f);
    const float* wp = W + (size_t)k0 * H1 + jbase;
    const float* xp = tile + r * CHUNK;

    #pragma unroll 8
    for (int kk = 0; kk < CHUNK; kk++) {
        float4 wv = *(const float4*)(wp + (size_t)kk * H1);
        float  xv = xp[kk];
        acc.x += xv * wv.x;
        acc.y += xv * wv.y;
        acc.z += xv * wv.z;
        acc.w += xv * wv.w;
    }

    *(float4*)(part + (size_t)blockIdx.z * NSEG * H1 + (size_t)(rbase + r) * H1 + jbase) = acc;
}

// Reduce partials + bias + LeakyReLU(0.01). One CTA per row (64), 256 threads.
__global__ __launch_bounds__(256)
void mlp_reduce_kernel(const float* __restrict__ b, float* __restrict__ out)
{
    const int row = blockIdx.x;
    const int c4  = threadIdx.x * 4;
    float4 a = make_float4(0.f, 0.f, 0.f, 0.f);
    #pragma unroll
    for (int z = 0; z < KSLICES; z++) {
        float4 p = *(const float4*)(g_part + (size_t)z * NSEG * H1 + (size_t)row * H1 + c4);
        a.x += p.x; a.y += p.y; a.z += p.z; a.w += p.w;
    }
    const float4 bb = *(const float4*)(b + c4);
    float4 o;
    o.x = a.x + bb.x; o.x = o.x > 0.f ? o.x : 0.01f * o.x;
    o.y = a.y + bb.y; o.y = o.y > 0.f ? o.y : 0.01f * o.y;
    o.z = a.z + bb.z; o.z = o.z > 0.f ? o.z : 0.01f * o.z;
    o.w = a.w + bb.w; o.w = o.w > 0.f ? o.w : 0.01f * o.w;
    *(float4*)(out + (size_t)row * H1 + c4) = o;
}

// ---------------------------------------------------------------------------
// Kernel 5: head (64,1024)@(1024,6) + bias, sigmoid. One warp per segment.
// ---------------------------------------------------------------------------
__global__ __launch_bounds__(32)
void head_kernel(const float* __restrict__ W3, const float* __restrict__ b3,
                 float* __restrict__ out)
{
    const int g    = blockIdx.x;
    const int lane = threadIdx.x;
    float p[NCLS] = {0.f, 0.f, 0.f, 0.f, 0.f, 0.f};

    for (int k = lane; k < H1; k += 32) {
        float x = g_h2[(size_t)g * H1 + k];
        #pragma unroll
        for (int j = 0; j < NCLS; j++)
            p[j] += x * W3[k * NCLS + j];
    }
    #pragma unroll
    for (int j = 0; j < NCLS; j++) {
        #pragma unroll
        for (int o = 16; o > 0; o >>= 1)
            p[j] += __shfl_xor_sync(0xffffffffu, p[j], o);
    }
    if (lane < NCLS) {
        float v = p[lane] + b3[lane];
        out[g * NCLS + lane] = 1.f / (1.f + expf(-v));
    }
}

// ---------------------------------------------------------------------------
extern "C" void kernel_launch(void* const* d_in, const int* in_sizes, int n_in,
                              void* d_out, int out_size)
{
    (void)in_sizes; (void)n_in; (void)out_size;
    const float* emb = (const float*)d_in[0];
    const float* pos = (const float*)d_in[1];
    const float* Wa  = (const float*)d_in[2];
    const float* ba  = (const float*)d_in[3];
    const float* W1  = (const float*)d_in[4];
    const float* b1  = (const float*)d_in[5];
    const float* W2  = (const float*)d_in[6];
    const float* b2  = (const float*)d_in[7];
    const float* W3  = (const float*)d_in[8];
    const float* b3  = (const float*)d_in[9];
    const int*   seg = (const int*)d_in[10];
    float* out = (float*)d_out;

    void *p_vecs = nullptr, *p_h1 = nullptr, *p_h2 = nullptr, *p_part = nullptr;
    cudaGetSymbolAddress(&p_vecs, g_vecs);
    cudaGetSymbolAddress(&p_h1, g_h1);
    cudaGetSymbolAddress(&p_h2, g_h2);
    cudaGetSymbolAddress(&p_part, g_part);

    // Pool split into 4 launches (independent slice ranges). The 4th launch
    // is the one ncu captures -> pool metrics become visible.
    pool_part_kernel<<<dim3(S_SEG, 4), 256>>>(emb, pos, Wa, ba, 0);
    pool_part_kernel<<<dim3(S_SEG, 4), 256>>>(emb, pos, Wa, ba, 4);
    pool_part_kernel<<<dim3(S_SEG, 4), 256>>>(emb, pos, Wa, ba, 8);
    pool_part_kernel<<<dim3(S_SEG, 4), 256>>>(emb, pos, Wa, ba, 12);

    pool_merge_kernel<<<S_SEG, 192>>>();
    segsum_kernel<<<NSEG, 256>>>(seg);

    mlp_splitk_kernel<BERT><<<dim3(16, 8, KSLICES), 128>>>(
        (const float*)p_vecs, W1, (float*)p_part);
    mlp_reduce_kernel<<<NSEG, 256>>>(b1, (float*)p_h1);

    mlp_splitk_kernel<H1><<<dim3(16, 8, KSLICES), 128>>>(
        (const float*)p_h1, W2, (float*)p_part);
    mlp_reduce_kernel<<<NSEG, 256>>>(b2, (float*)p_h2);

    head_kernel<<<NSEG, 32>>>(W3, b3, out);
}